// round 10
// baseline (speedup 1.0000x reference)
#include <cuda_runtime.h>
#include <cstdint>
#include <math_constants.h>

// Sparsemax (faithful-to-buggy-reference): per contiguous row of K=2048:
//   r = inclusive cumsum(z); unmasked_k: 1 + k*z_k > r_k (1-indexed)
//   kmax = max unmasked k; tmax = max unmasked r_k
//   tau = (tmax-1)/kmax; out = max(0, z - tau)
//
// R10 (= R9 resubmitted after infra failure): FOUR independent rows per
// CTA of 512 threads (16 warps); every thread holds one float4 of each row
// (512*4 = 2048 = K). All serial sections (warp shuffle scan, cross-warp
// combine, REDUX maxes) run as 4 interleaved independent chains (ILP=4),
// and the two __syncthreads serve 4 rows (0.5 barriers/row, half of R8).

constexpr int K       = 2048;
constexpr int THREADS = 512;
constexpr int RPC     = 4;              // rows per CTA
constexpr int EPT     = 4;              // elems per row per thread
constexpr int NW      = THREADS / 32;   // 16 warps
constexpr int ROWF4   = K / 4;          // 512 float4 per row

static_assert(THREADS * EPT == K, "full row coverage");

__device__ __forceinline__ unsigned f2ord(float f) {
    unsigned u = __float_as_uint(f);
    return (u & 0x80000000u) ? ~u : (u | 0x80000000u);
}
__device__ __forceinline__ float ord2f(unsigned u) {
    return __uint_as_float((u & 0x80000000u) ? (u ^ 0x80000000u) : ~u);
}

__global__ __launch_bounds__(THREADS)
void sparsemax_rowwise_kernel(const float* __restrict__ x, float* __restrict__ y,
                              int nrows)
{
    const int tid  = threadIdx.x;
    const int lane = tid & 31;
    const int wid  = tid >> 5;
    const int row0 = blockIdx.x * RPC;

    const float4* __restrict__ xbase = reinterpret_cast<const float4*>(x) + tid;

    // Per-row indices; alias missing rows to row0 (stores are guarded)
    int ridx[RPC];
    #pragma unroll
    for (int r = 0; r < RPC; r++)
        ridx[r] = (row0 + r < nrows) ? (row0 + r) : row0;

    // 4 independent LDG.128 in flight
    float4 v[RPC];
    #pragma unroll
    for (int r = 0; r < RPC; r++)
        v[r] = xbase[(size_t)ridx[r] * ROWF4];

    // Per-thread totals (4 independent 2-level trees)
    float tot[RPC];
    #pragma unroll
    for (int r = 0; r < RPC; r++)
        tot[r] = (v[r].x + v[r].y) + (v[r].z + v[r].w);

    // 4 interleaved warp inclusive scans
    float sc[RPC];
    #pragma unroll
    for (int r = 0; r < RPC; r++) sc[r] = tot[r];
    #pragma unroll
    for (int o = 1; o < 32; o <<= 1) {
        float t[RPC];
        #pragma unroll
        for (int r = 0; r < RPC; r++)
            t[r] = __shfl_up_sync(0xffffffffu, sc[r], o);
        if (lane >= o) {
            #pragma unroll
            for (int r = 0; r < RPC; r++) sc[r] += t[r];
        }
    }

    __shared__ float    wsum[RPC][NW];
    __shared__ unsigned wkt[2 * RPC][NW];   // k0..k3, t0..t3

    if (lane == 31) {
        #pragma unroll
        for (int r = 0; r < RPC; r++) wsum[r][wid] = sc[r];
    }
    __syncthreads();

    // Lane-parallel cross-warp exclusive offsets: 16-lane shuffle scan x4
    {
        const int g = lane & 15;
        float vw[RPC];
        #pragma unroll
        for (int r = 0; r < RPC; r++) vw[r] = wsum[r][g];
        #pragma unroll
        for (int o = 1; o < NW; o <<= 1) {
            float t[RPC];
            #pragma unroll
            for (int r = 0; r < RPC; r++)
                t[r] = __shfl_up_sync(0xffffffffu, vw[r], o);
            if (g >= o) {
                #pragma unroll
                for (int r = 0; r < RPC; r++) vw[r] += t[r];
            }
        }
        #pragma unroll
        for (int r = 0; r < RPC; r++) {
            float inc = __shfl_sync(0xffffffffu, vw[r], wid);
            // exclusive base for this thread's element 0 of row r
            sc[r] += inc - wsum[r][wid] - tot[r];
        }
    }

    // Running prefix + mask maxes (4 interleaved chains)
    const float kb = (float)(tid * EPT);
    float kmax[RPC], tmax[RPC];
    #pragma unroll
    for (int r = 0; r < RPC; r++) { kmax[r] = 0.0f; tmax[r] = -CUDART_INF_F; }

    #pragma unroll
    for (int e = 0; e < EPT; e++) {
        const float kk = kb + (float)(e + 1);
        #pragma unroll
        for (int r = 0; r < RPC; r++) {
            const float ze = (e == 0) ? v[r].x : (e == 1) ? v[r].y
                           : (e == 2) ? v[r].z : v[r].w;
            sc[r] += ze;                       // running inclusive prefix
            if (fmaf(kk, ze, 1.0f) > sc[r]) {
                kmax[r] = fmaxf(kmax[r], kk);
                tmax[r] = fmaxf(tmax[r], sc[r]);
            }
        }
    }

    // Warp-level REDUX (8 independent ops), then cross-warp combine
    unsigned ku[RPC], tu[RPC];
    #pragma unroll
    for (int r = 0; r < RPC; r++) {
        ku[r] = __reduce_max_sync(0xffffffffu, __float2uint_rz(kmax[r]));
        tu[r] = __reduce_max_sync(0xffffffffu, f2ord(tmax[r]));
    }
    if (lane == 0) {
        #pragma unroll
        for (int r = 0; r < RPC; r++) {
            wkt[r][wid]       = ku[r];
            wkt[RPC + r][wid] = tu[r];
        }
    }
    __syncthreads();

    // Masked full-warp REDUX over 16 per-warp values (identity 0 safe:
    // f2ord > 0 always, kmax counts >= 1).
    const bool in16 = (lane < NW);
    float tau[RPC];
    #pragma unroll
    for (int r = 0; r < RPC; r++) {
        unsigned km = __reduce_max_sync(0xffffffffu, in16 ? wkt[r][lane] : 0u);
        unsigned tm = __reduce_max_sync(0xffffffffu, in16 ? wkt[RPC + r][lane] : 0u);
        tau[r] = __fdividef(ord2f(tm) - 1.0f, __uint2float_rn(km));
    }

    // Outputs (streaming stores; guarded per row)
    float4* __restrict__ ybase = reinterpret_cast<float4*>(y) + tid;
    #pragma unroll
    for (int r = 0; r < RPC; r++) {
        if (row0 + r < nrows) {
            float4 o;
            o.x = fmaxf(0.0f, v[r].x - tau[r]);
            o.y = fmaxf(0.0f, v[r].y - tau[r]);
            o.z = fmaxf(0.0f, v[r].z - tau[r]);
            o.w = fmaxf(0.0f, v[r].w - tau[r]);
            __stcs(ybase + (size_t)(row0 + r) * ROWF4, o);
        }
    }
}

extern "C" void kernel_launch(void* const* d_in, const int* in_sizes, int n_in,
                              void* d_out, int out_size)
{
    const float* x = (const float*)d_in[0];
    float*       y = (float*)d_out;
    const int rows = out_size / K;                 // 8192 for the bench shape
    const int grid = (rows + RPC - 1) / RPC;       // 2048
    sparsemax_rowwise_kernel<<<grid, THREADS>>>(x, y, rows);
}